// round 5
// baseline (speedup 1.0000x reference)
#include <cuda_runtime.h>
#include <cuda_bf16.h>
#include <cstdint>

#define BDIM 16384
#define CDIM 1024
#define DDIM 128
#define LOG2E 1.4426950408889634f

// ------------------------------- scratch -------------------------------
__device__ float s_theta[BDIM * DDIM];
__device__ float s_phi[BDIM * DDIM];
__device__ float s_g[BDIM * DDIM];

// A fragment-split buffers: [mtile][ktile][lane][{hi,lo} x 16B]
// x: 1024 mtiles x 64 ktiles x 32 lanes x 2 uint4
__device__ uint4 s_x0s[1024 * 64 * 32 * 2];
__device__ uint4 s_x1s[1024 * 64 * 32 * 2];
// y: 1024 mtiles x 8 ktiles x 32 lanes x 2 uint4
__device__ uint4 s_ys[1024 * 8 * 32 * 2];

__device__ __nv_bfloat16 s_gwh[DDIM * CDIM];
__device__ __nv_bfloat16 s_gwl[DDIM * CDIM];
__device__ __nv_bfloat16 s_thwh[DDIM * CDIM];
__device__ __nv_bfloat16 s_thwl[DDIM * CDIM];
__device__ __nv_bfloat16 s_phwh[DDIM * CDIM];
__device__ __nv_bfloat16 s_phwl[DDIM * CDIM];
__device__ __nv_bfloat16 s_Wwh[CDIM * DDIM];
__device__ __nv_bfloat16 s_Wwl[CDIM * DDIM];

// ------------------------------- helpers -------------------------------
__device__ __forceinline__ unsigned pkb(__nv_bfloat16 a, __nv_bfloat16 b) {
    return (unsigned)__bfloat16_as_ushort(a) | ((unsigned)__bfloat16_as_ushort(b) << 16);
}
__device__ __forceinline__ void ldsm4(uint32_t* r, uint32_t addr) {
    asm volatile("ldmatrix.sync.aligned.m8n8.x4.shared.b16 {%0,%1,%2,%3}, [%4];"
                 : "=r"(r[0]), "=r"(r[1]), "=r"(r[2]), "=r"(r[3]) : "r"(addr));
}
__device__ __forceinline__ void mma16816(float* c, const uint32_t* a, uint32_t b0, uint32_t b1) {
    asm volatile(
        "mma.sync.aligned.m16n8k16.row.col.f32.bf16.bf16.f32 "
        "{%0,%1,%2,%3}, {%4,%5,%6,%7}, {%8,%9}, {%0,%1,%2,%3};"
        : "+f"(c[0]), "+f"(c[1]), "+f"(c[2]), "+f"(c[3])
        : "r"(a[0]), "r"(a[1]), "r"(a[2]), "r"(a[3]), "r"(b0), "r"(b1));
}
__device__ __forceinline__ void cp16(uint32_t dst, const void* src) {
    asm volatile("cp.async.cg.shared.global [%0], [%1], 16;" :: "r"(dst), "l"(src));
}
#define CP_COMMIT() asm volatile("cp.async.commit_group;")
__device__ __forceinline__ float ex2f(float x) {
    float r; asm("ex2.approx.ftz.f32 %0, %1;" : "=f"(r) : "f"(x)); return r;
}

// ---------------- fused weight hi/lo split ----------------
__global__ void split4_kernel(const float* __restrict__ w0, const float* __restrict__ w1,
                              const float* __restrict__ w2, const float* __restrict__ w3) {
    int wsel = blockIdx.y;
    const float* in = wsel == 0 ? w0 : wsel == 1 ? w1 : wsel == 2 ? w2 : w3;
    __nv_bfloat16* hi = wsel == 0 ? s_gwh : wsel == 1 ? s_thwh : wsel == 2 ? s_phwh : s_Wwh;
    __nv_bfloat16* lo = wsel == 0 ? s_gwl : wsel == 1 ? s_thwl : wsel == 2 ? s_phwl : s_Wwl;
    const int n4 = DDIM * CDIM / 4;
    const float4* in4 = reinterpret_cast<const float4*>(in);
    uint2* hp = reinterpret_cast<uint2*>(hi);
    uint2* lp = reinterpret_cast<uint2*>(lo);
    for (int i = blockIdx.x * blockDim.x + threadIdx.x; i < n4; i += gridDim.x * blockDim.x) {
        float4 v = in4[i];
        __nv_bfloat16 a = __float2bfloat16(v.x), b = __float2bfloat16(v.y);
        __nv_bfloat16 c = __float2bfloat16(v.z), d = __float2bfloat16(v.w);
        __nv_bfloat16 e = __float2bfloat16(v.x - __bfloat162float(a));
        __nv_bfloat16 f = __float2bfloat16(v.y - __bfloat162float(b));
        __nv_bfloat16 g = __float2bfloat16(v.z - __bfloat162float(c));
        __nv_bfloat16 h = __float2bfloat16(v.w - __bfloat162float(d));
        hp[i] = make_uint2(pkb(a, b), pkb(c, d));
        lp[i] = make_uint2(pkb(e, f), pkb(g, h));
    }
}

// ---------------- A prepass: fp32 x -> hi/lo bf16 fragments ----------------
// thread -> (tile, lane). tile = mt*64 + kt.  frag: a0=(r,c),a1=(r+8,c),a2=(r,c+8),a3=(r+8,c+8)
__global__ void __launch_bounds__(256)
prepass_kernel(const float* __restrict__ x0, const float* __restrict__ x1) {
    const float* x = blockIdx.y ? x1 : x0;
    uint4* dst = blockIdx.y ? s_x1s : s_x0s;
    int tile = blockIdx.x * 8 + (threadIdx.x >> 5);
    int lane = threadIdx.x & 31;
    int mt = tile >> 6, kt = tile & 63;
    int r0 = mt * 16 + (lane >> 2), c0 = kt * 16 + (lane & 3) * 2;
    const float* p = x + (size_t)r0 * CDIM + c0;
    float2 v0 = *reinterpret_cast<const float2*>(p);
    float2 v1 = *reinterpret_cast<const float2*>(p + 8 * CDIM);
    float2 v2 = *reinterpret_cast<const float2*>(p + 8);
    float2 v3 = *reinterpret_cast<const float2*>(p + 8 * CDIM + 8);
    __nv_bfloat16 h0 = __float2bfloat16(v0.x), h1 = __float2bfloat16(v0.y);
    __nv_bfloat16 h2 = __float2bfloat16(v1.x), h3 = __float2bfloat16(v1.y);
    __nv_bfloat16 h4 = __float2bfloat16(v2.x), h5 = __float2bfloat16(v2.y);
    __nv_bfloat16 h6 = __float2bfloat16(v3.x), h7 = __float2bfloat16(v3.y);
    __nv_bfloat16 l0 = __float2bfloat16(v0.x - __bfloat162float(h0));
    __nv_bfloat16 l1 = __float2bfloat16(v0.y - __bfloat162float(h1));
    __nv_bfloat16 l2 = __float2bfloat16(v1.x - __bfloat162float(h2));
    __nv_bfloat16 l3 = __float2bfloat16(v1.y - __bfloat162float(h3));
    __nv_bfloat16 l4 = __float2bfloat16(v2.x - __bfloat162float(h4));
    __nv_bfloat16 l5 = __float2bfloat16(v2.y - __bfloat162float(h5));
    __nv_bfloat16 l6 = __float2bfloat16(v3.x - __bfloat162float(h6));
    __nv_bfloat16 l7 = __float2bfloat16(v3.y - __bfloat162float(h7));
    size_t idx = ((size_t)tile * 32 + lane) * 2;
    dst[idx]     = make_uint4(pkb(h0, h1), pkb(h2, h3), pkb(h4, h5), pkb(h6, h7));
    dst[idx + 1] = make_uint4(pkb(l0, l1), pkb(l2, l3), pkb(l4, l5), pkb(l6, l7));
}

// ---------------- split GEMM: out[128,128] = A[128,K] @ W[128,K]^T (+bias)(+resid) ----------------
// 8 warps: 2m x 4n; warp tile 64x32. A frags from GMEM (LDG.128), W via 4-buffer cp.async + ldsm.
#define SAP 40
#define WBUF 20480
#define GSMEM (4 * WBUF)

__device__ __forceinline__ void gemm_body(
    const uint4* __restrict__ As, int gmt0, int KT, int NC,
    const __nv_bfloat16* __restrict__ Wh, const __nv_bfloat16* __restrict__ Wl, int K,
    const float* __restrict__ bias, const float* __restrict__ resid,
    float* __restrict__ out, int ldo) {
    extern __shared__ unsigned char smem[];
    const int tid = threadIdx.x, lane = tid & 31, wid = tid >> 5;
    const int wm = (wid & 1) * 64, wn = (wid >> 1) * 32;
    const uint32_t sbase = (uint32_t)__cvta_generic_to_shared(smem);

    float acc[4][4][4];
#pragma unroll
    for (int a = 0; a < 4; a++)
#pragma unroll
        for (int b = 0; b < 4; b++)
#pragma unroll
            for (int c = 0; c < 4; c++) acc[a][b][c] = 0.f;

#define CPW(kc) do {                                                          \
        int _b = (kc) & 3, _kk = (kc) * 32;                                   \
        uint32_t _base = sbase + (uint32_t)_b * WBUF;                         \
        _Pragma("unroll")                                                     \
        for (int _i = 0; _i < 2; _i++) {                                      \
            int _q = tid + 256 * _i;                                          \
            int _r = _q >> 2, _cc = _q & 3;                                   \
            uint32_t _d = _base + (uint32_t)(_r * SAP + _cc * 8) * 2;         \
            cp16(_d, Wh + (size_t)_r * K + _kk + _cc * 8);                    \
            cp16(_d + 10240, Wl + (size_t)_r * K + _kk + _cc * 8);            \
        }                                                                     \
        CP_COMMIT();                                                          \
    } while (0)

    uint4 cur[8], nxt[8];
#define LDA(dst, kt) do {                                                     \
        _Pragma("unroll")                                                     \
        for (int _mt = 0; _mt < 4; _mt++) {                                   \
            size_t _idx = ((size_t)((gmt0 + (wid & 1) * 4 + _mt) * KT + (kt)) * 32 + lane) * 2; \
            (dst)[2 * _mt] = As[_idx];                                        \
            (dst)[2 * _mt + 1] = As[_idx + 1];                                \
        }                                                                     \
    } while (0)

    CPW(0);
    CPW(1);
    LDA(cur, 0);

    for (int kc = 0; kc < NC; kc++) {
        if (kc + 2 < NC) {
            CPW(kc + 2);
            asm volatile("cp.async.wait_group 2;");
        } else if (kc + 1 < NC) {
            asm volatile("cp.async.wait_group 1;");
        } else {
            asm volatile("cp.async.wait_group 0;");
        }
        __syncthreads();
        const uint32_t wb = sbase + (uint32_t)(kc & 3) * WBUF;
#pragma unroll
        for (int ks = 0; ks < 2; ks++) {
            uint32_t wf0[4], wf1[4];
            const uint32_t w0off = (uint32_t)(((wn + (lane & 7) + ((lane >> 4) & 1) * 8) * SAP) +
                                              ks * 16 + ((lane >> 3) & 1) * 8) * 2;
            const uint32_t w1off = (uint32_t)(((wn + 16 + (lane & 7) + ((lane >> 4) & 1) * 8) * SAP) +
                                              ks * 16 + ((lane >> 3) & 1) * 8) * 2;
            ldsm4(wf0, wb + w0off);
            ldsm4(wf1, wb + w1off);
            int ktn = kc * 2 + ks + 1;
            if (ktn > KT - 1) ktn = KT - 1;
            LDA(nxt, ktn);
#pragma unroll
            for (int mt = 0; mt < 4; mt++) {
                const uint32_t* ah = reinterpret_cast<const uint32_t*>(&cur[2 * mt]);
                const uint32_t* al = reinterpret_cast<const uint32_t*>(&cur[2 * mt + 1]);
                mma16816(acc[mt][0], ah, wf0[0], wf0[1]);
                mma16816(acc[mt][1], ah, wf0[2], wf0[3]);
                mma16816(acc[mt][2], ah, wf1[0], wf1[1]);
                mma16816(acc[mt][3], ah, wf1[2], wf1[3]);
                mma16816(acc[mt][0], al, wf0[0], wf0[1]);
                mma16816(acc[mt][1], al, wf0[2], wf0[3]);
                mma16816(acc[mt][2], al, wf1[0], wf1[1]);
                mma16816(acc[mt][3], al, wf1[2], wf1[3]);
            }
            ldsm4(wf0, wb + 10240 + w0off);
            ldsm4(wf1, wb + 10240 + w1off);
#pragma unroll
            for (int mt = 0; mt < 4; mt++) {
                const uint32_t* ah = reinterpret_cast<const uint32_t*>(&cur[2 * mt]);
                mma16816(acc[mt][0], ah, wf0[0], wf0[1]);
                mma16816(acc[mt][1], ah, wf0[2], wf0[3]);
                mma16816(acc[mt][2], ah, wf1[0], wf1[1]);
                mma16816(acc[mt][3], ah, wf1[2], wf1[3]);
            }
#pragma unroll
            for (int i = 0; i < 8; i++) cur[i] = nxt[i];
        }
    }

#pragma unroll
    for (int mt = 0; mt < 4; mt++) {
        int r = wm + mt * 16 + (lane >> 2);
#pragma unroll
        for (int np = 0; np < 4; np++) {
            int c = wn + np * 8 + (lane & 3) * 2;
            float b0 = bias[c], b1 = bias[c + 1];
            float2 v0 = make_float2(acc[mt][np][0] + b0, acc[mt][np][1] + b1);
            float2 v1 = make_float2(acc[mt][np][2] + b0, acc[mt][np][3] + b1);
            size_t i0 = (size_t)r * ldo + c;
            size_t i1 = (size_t)(r + 8) * ldo + c;
            if (resid) {
                v0.x += resid[i0]; v0.y += resid[i0 + 1];
                v1.x += resid[i1]; v1.y += resid[i1 + 1];
            }
            *reinterpret_cast<float2*>(&out[i0]) = v0;
            *reinterpret_cast<float2*>(&out[i1]) = v1;
        }
    }
#undef CPW
#undef LDA
}

// grid (3, 128): x = {g, theta, phi}, y = row tile
__global__ void __launch_bounds__(256)
proj_gemm(const float* __restrict__ gb, const float* __restrict__ thb,
          const float* __restrict__ phb) {
    int bz = blockIdx.x;
    const uint4* As = bz == 0 ? s_x0s : s_x1s;
    const __nv_bfloat16* Wh = bz == 0 ? s_gwh : bz == 1 ? s_thwh : s_phwh;
    const __nv_bfloat16* Wl = bz == 0 ? s_gwl : bz == 1 ? s_thwl : s_phwl;
    const float* bias = bz == 0 ? gb : bz == 1 ? thb : phb;
    float* out = (bz == 0 ? s_g : bz == 1 ? s_theta : s_phi) + (size_t)blockIdx.y * 128 * DDIM;
    gemm_body(As, blockIdx.y * 8, 64, 32, Wh, Wl, CDIM, bias, nullptr, out, DDIM);
}

// grid (8, 128): x = n tile, y = row tile
__global__ void __launch_bounds__(256)
out_gemm(const float* __restrict__ Wb, const float* __restrict__ x0, float* __restrict__ out) {
    size_t n0 = (size_t)blockIdx.x * 128;
    size_t bm = (size_t)blockIdx.y * 128;
    gemm_body(s_ys, blockIdx.y * 8, 8, 4, s_Wwh + n0 * DDIM, s_Wwl + n0 * DDIM, DDIM,
              Wb + n0, x0 + bm * CDIM + n0, out + bm * CDIM + n0, CDIM);
}

// ---------------- rank-1 softmax attention; emits y in split-fragment layout ----------------
// block = 16 rows (one mtile), 512 threads: warp w = row w, lane handles 4 cols.
__global__ void __launch_bounds__(512)
attn16_kernel() {
    __shared__ float sth[16 * 128], sg[16 * 128], sph[16 * 128], sy[16 * 128];
    const int tid = threadIdx.x;
    const size_t base = (size_t)blockIdx.x * 16 * 128;
    reinterpret_cast<float4*>(sth)[tid] = reinterpret_cast<const float4*>(s_theta + base)[tid];
    reinterpret_cast<float4*>(sg)[tid]  = reinterpret_cast<const float4*>(s_g + base)[tid];
    reinterpret_cast<float4*>(sph)[tid] = reinterpret_cast<const float4*>(s_phi + base)[tid];
    __syncwarp();

    const int w = tid >> 5, l = tid & 31;
    const float* th = sth + w * 128;
    const float* gg = sg + w * 128;
    const float* ph = sph + w * 128;

    float a0 = th[l], a1 = th[l + 32], a2 = th[l + 64], a3 = th[l + 96];
    float mx = fmaxf(fmaxf(a0, a1), fmaxf(a2, a3));
    float mn = fminf(fminf(a0, a1), fminf(a2, a3));
#pragma unroll
    for (int off = 16; off >= 1; off >>= 1) {
        mx = fmaxf(mx, __shfl_xor_sync(0xffffffffu, mx, off));
        mn = fminf(mn, __shfl_xor_sync(0xffffffffu, mn, off));
    }
    float sc[4], m2n[4], num[4], den[4];
#pragma unroll
    for (int q = 0; q < 4; q++) {
        sc[q] = ph[l + 32 * q] * LOG2E;
        m2n[q] = -sc[q] * (sc[q] >= 0.f ? mx : mn);
        num[q] = 0.f; den[q] = 0.f;
    }
#pragma unroll 8
    for (int j = 0; j < 128; j += 4) {
        float4 tv = *reinterpret_cast<const float4*>(&th[j]);
        float4 gv = *reinterpret_cast<const float4*>(&gg[j]);
        float t_[4] = {tv.x, tv.y, tv.z, tv.w};
        float g_[4] = {gv.x, gv.y, gv.z, gv.w};
#pragma unroll
        for (int e = 0; e < 4; e++) {
#pragma unroll
            for (int q = 0; q < 4; q++) {
                float ex = ex2f(fmaf(sc[q], t_[e], m2n[q]));
                num[q] = fmaf(ex, g_[e], num[q]);
                den[q] += ex;
            }
        }
    }
#pragma unroll
    for (int q = 0; q < 4; q++) sy[w * 128 + l + 32 * q] = num[q] / den[q];
    __syncthreads();

    // write y fragments: thread -> (kt, lane, part)
    const int kt = tid >> 6, lane2 = (tid >> 1) & 31, part = tid & 1;
    const int r0 = lane2 >> 2, c0 = kt * 16 + (lane2 & 3) * 2;
    float v[8] = {sy[r0 * 128 + c0],       sy[r0 * 128 + c0 + 1],
                  sy[(r0 + 8) * 128 + c0], sy[(r0 + 8) * 128 + c0 + 1],
                  sy[r0 * 128 + c0 + 8],   sy[r0 * 128 + c0 + 9],
                  sy[(r0 + 8) * 128 + c0 + 8], sy[(r0 + 8) * 128 + c0 + 9]};
    __nv_bfloat16 h[8];
#pragma unroll
    for (int i = 0; i < 8; i++) h[i] = __float2bfloat16(v[i]);
    uint4 o;
    if (part == 0) {
        o = make_uint4(pkb(h[0], h[1]), pkb(h[2], h[3]), pkb(h[4], h[5]), pkb(h[6], h[7]));
    } else {
        __nv_bfloat16 lo[8];
#pragma unroll
        for (int i = 0; i < 8; i++) lo[i] = __float2bfloat16(v[i] - __bfloat162float(h[i]));
        o = make_uint4(pkb(lo[0], lo[1]), pkb(lo[2], lo[3]), pkb(lo[4], lo[5]), pkb(lo[6], lo[7]));
    }
    s_ys[((size_t)(blockIdx.x * 8 + kt) * 32 + lane2) * 2 + part] = o;
}

// ------------------------------- launch -------------------------------
extern "C" void kernel_launch(void* const* d_in, const int* in_sizes, int n_in,
                              void* d_out, int out_size) {
    const float* x0   = (const float*)d_in[0];
    const float* x1   = (const float*)d_in[1];
    const float* g_w  = (const float*)d_in[2];
    const float* g_b  = (const float*)d_in[3];
    const float* th_w = (const float*)d_in[4];
    const float* th_b = (const float*)d_in[5];
    const float* ph_w = (const float*)d_in[6];
    const float* ph_b = (const float*)d_in[7];
    const float* W_w  = (const float*)d_in[8];
    const float* W_b  = (const float*)d_in[9];
    float* out = (float*)d_out;

    cudaFuncSetAttribute(proj_gemm, cudaFuncAttributeMaxDynamicSharedMemorySize, GSMEM);
    cudaFuncSetAttribute(out_gemm, cudaFuncAttributeMaxDynamicSharedMemorySize, GSMEM);

    split4_kernel<<<dim3(32, 4), 256>>>(g_w, th_w, ph_w, W_w);
    prepass_kernel<<<dim3(8192, 2), 256>>>(x0, x1);

    proj_gemm<<<dim3(3, BDIM / 128), 256, GSMEM>>>(g_b, th_b, ph_b);

    attn16_kernel<<<BDIM / 16, 512>>>();

    out_gemm<<<dim3(8, BDIM / 128), 256, GSMEM>>>(W_b, x0, out);
}